// round 14
// baseline (speedup 1.0000x reference)
#include <cuda_runtime.h>
#include <cuda_bf16.h>
#include <math.h>

#define TOK   4096     // B*T
#define DIMV  512
#define DQ    1024
#define NKEY  256
#define DH    128
#define NHEAD 4

// ---------------- scratch (no allocations allowed) ----------------
__device__ float g_q[TOK * DQ];          // 16 MB
__device__ float g_dots[TOK * 2048];     // 32 MB  [token][h][p][n]

// =================== q-proj GEMM + fused LayerNorm epilogue ===================
// 128x128 tile, 8x8/thread, ascending fused-FMA chain (frozen numerics).
// Each tile spans one full 128-dim LN row-chunk; LN stats via fp64 (proven-neutral class).
#define QBM 128
#define QBN 128
#define QBK 16

__global__ __launch_bounds__(256) void gemm_asc_ln(
    const float* __restrict__ A, int lda,
    const float* __restrict__ B, int ldb,
    float* __restrict__ C, int ldc, int K,
    const float* __restrict__ lng, const float* __restrict__ lnb)
{
    __shared__ float As[QBK][132];
    __shared__ float Bs[QBK][132];

    const int tid = threadIdx.x;
    const int tx = tid & 15;
    const int ty = tid >> 4;
    const int m0 = blockIdx.y * QBM;
    const int n0 = blockIdx.x * QBN;

    const int lrow = tid >> 1;
    const int lk   = (tid & 1) * 8;

    const float* Ab = A + (size_t)(m0 + lrow) * lda + lk;
    const float* Bb = B + (size_t)(n0 + lrow) * ldb + lk;

    float acc[8][8];
#pragma unroll
    for (int i = 0; i < 8; i++)
#pragma unroll
        for (int j = 0; j < 8; j++) acc[i][j] = 0.f;

    float4 va0 = *(const float4*)(Ab);
    float4 va1 = *(const float4*)(Ab + 4);
    float4 vb0 = *(const float4*)(Bb);
    float4 vb1 = *(const float4*)(Bb + 4);

    for (int k0 = 0; k0 < K; k0 += QBK) {
        As[lk + 0][lrow] = va0.x; As[lk + 1][lrow] = va0.y;
        As[lk + 2][lrow] = va0.z; As[lk + 3][lrow] = va0.w;
        As[lk + 4][lrow] = va1.x; As[lk + 5][lrow] = va1.y;
        As[lk + 6][lrow] = va1.z; As[lk + 7][lrow] = va1.w;
        Bs[lk + 0][lrow] = vb0.x; Bs[lk + 1][lrow] = vb0.y;
        Bs[lk + 2][lrow] = vb0.z; Bs[lk + 3][lrow] = vb0.w;
        Bs[lk + 4][lrow] = vb1.x; Bs[lk + 5][lrow] = vb1.y;
        Bs[lk + 6][lrow] = vb1.z; Bs[lk + 7][lrow] = vb1.w;
        __syncthreads();

        if (k0 + QBK < K) {
            va0 = *(const float4*)(Ab + k0 + QBK);
            va1 = *(const float4*)(Ab + k0 + QBK + 4);
            vb0 = *(const float4*)(Bb + k0 + QBK);
            vb1 = *(const float4*)(Bb + k0 + QBK + 4);
        }

#pragma unroll
        for (int kk = 0; kk < QBK; kk++) {
            float a[8], b[8];
            *(float4*)(a)     = *(const float4*)(&As[kk][ty * 8]);
            *(float4*)(a + 4) = *(const float4*)(&As[kk][ty * 8 + 4]);
            *(float4*)(b)     = *(const float4*)(&Bs[kk][tx * 8]);
            *(float4*)(b + 4) = *(const float4*)(&Bs[kk][tx * 8 + 4]);
#pragma unroll
            for (int i = 0; i < 8; i++)
#pragma unroll
                for (int j = 0; j < 8; j++)
                    acc[i][j] = fmaf(a[i], b[j], acc[i][j]);   // ascending fused chain (frozen)
        }
        __syncthreads();
    }

    // ---- fused LayerNorm over each row of this 128-col tile ----
    // Row r = m0+ty*8+i is held by the 16 threads sharing ty (lanes form width-16 group).
    float gg[8], bb[8];
#pragma unroll
    for (int j = 0; j < 8; j++) {
        gg[j] = __ldg(lng + tx * 8 + j);
        bb[j] = __ldg(lnb + tx * 8 + j);
    }

#pragma unroll
    for (int i = 0; i < 8; i++) {
        // fp64-exact mean (LN numerics proven flip-neutral: R1≡R3≡R6)
        double s = 0.0;
#pragma unroll
        for (int j = 0; j < 8; j++) s += (double)acc[i][j];
#pragma unroll
        for (int off = 8; off; off >>= 1) s += __shfl_xor_sync(0xFFFFFFFFu, s, off, 16);
        const float mu = (float)(s * (1.0 / 128.0));

        float d[8];
#pragma unroll
        for (int j = 0; j < 8; j++) d[j] = __fadd_rn(acc[i][j], -mu);

        double ss = 0.0;
#pragma unroll
        for (int j = 0; j < 8; j++) ss += (double)d[j] * (double)d[j];
#pragma unroll
        for (int off = 8; off; off >>= 1) ss += __shfl_xor_sync(0xFFFFFFFFu, ss, off, 16);
        const float var = (float)(ss * (1.0 / 128.0));
        const float vpe = __fadd_rn(var, 1e-5f);
        const float r = (float)(1.0 / sqrt((double)vpe));

#pragma unroll
        for (int j = 0; j < 8; j++)
            acc[i][j] = __fadd_rn(__fmul_rn(__fmul_rn(d[j], r), gg[j]), bb[j]);
    }

#pragma unroll
    for (int i = 0; i < 8; i++) {
        float* Crow = C + (size_t)(m0 + ty * 8 + i) * ldc + n0 + tx * 8;
        *(float4*)(Crow)     = make_float4(acc[i][0], acc[i][1], acc[i][2], acc[i][3]);
        *(float4*)(Crow + 4) = make_float4(acc[i][4], acc[i][5], acc[i][6], acc[i][7]);
    }
}

// =================== dots GEMM: 4 k-strided fused chains, z-batched, reg-prefetched ===================
#define BM 64
#define BN 64
#define BK 16

__global__ __launch_bounds__(256) void gemm_dots_s4(
    const float* __restrict__ qbuf, const float* __restrict__ keys,
    float* __restrict__ dots)
{
    const int z = blockIdx.z;
    const int h = z >> 1, p = z & 1;
    const float* A = qbuf + (p * 4 + h) * 128;
    const float* B = keys + h * (NKEY * 2 * DH) + p * DH;
    float* C = dots + h * 512 + p * 256;
    const int lda = DQ, ldb = 2 * DH, ldc = 2048, K = DH;

    __shared__ float As[BK][BM];
    __shared__ float Bs[BK][BN];

    const int tid = threadIdx.x;
    const int tx = tid & 15;
    const int ty = tid >> 4;
    const int m0 = blockIdx.y * BM;
    const int n0 = blockIdx.x * BN;

    const int lrow = tid >> 2;
    const int lk   = (tid & 3) * 4;

    const float* Ab = A + (size_t)(m0 + lrow) * lda + lk;
    const float* Bb = B + (size_t)(n0 + lrow) * ldb + lk;

    float s[4][4][4];
#pragma unroll
    for (int i = 0; i < 4; i++)
#pragma unroll
        for (int j = 0; j < 4; j++)
#pragma unroll
            for (int c = 0; c < 4; c++) s[i][j][c] = 0.f;

    float4 va = *(const float4*)(Ab);
    float4 vb = *(const float4*)(Bb);

    for (int k0 = 0; k0 < K; k0 += BK) {
        As[lk + 0][lrow] = va.x; As[lk + 1][lrow] = va.y;
        As[lk + 2][lrow] = va.z; As[lk + 3][lrow] = va.w;
        Bs[lk + 0][lrow] = vb.x; Bs[lk + 1][lrow] = vb.y;
        Bs[lk + 2][lrow] = vb.z; Bs[lk + 3][lrow] = vb.w;
        __syncthreads();

        if (k0 + BK < K) {
            va = *(const float4*)(Ab + k0 + BK);
            vb = *(const float4*)(Bb + k0 + BK);
        }

#pragma unroll
        for (int kk = 0; kk < BK; kk++) {
            const int ch = kk & 3;
            float a[4], b[4];
#pragma unroll
            for (int i = 0; i < 4; i++) a[i] = As[kk][ty * 4 + i];
#pragma unroll
            for (int j = 0; j < 4; j++) b[j] = Bs[kk][tx * 4 + j];
#pragma unroll
            for (int i = 0; i < 4; i++)
#pragma unroll
                for (int j = 0; j < 4; j++)
                    s[i][j][ch] = fmaf(a[i], b[j], s[i][j][ch]);
        }
        __syncthreads();
    }

#pragma unroll
    for (int i = 0; i < 4; i++) {
        float* Crow = C + (size_t)(m0 + ty * 4 + i) * ldc + n0 + tx * 4;
#pragma unroll
        for (int j = 0; j < 4; j++) {
            float p01 = __fadd_rn(s[i][j][0], s[i][j][1]);
            float p23 = __fadd_rn(s[i][j][2], s[i][j][3]);
            Crow[j] = __fadd_rn(p01, p23);
        }
    }
}

// =================== top-k machinery (R11 two-REDUX version — known good) ===================
__device__ __forceinline__ unsigned int fkey(float f) {
    unsigned int u = __float_as_uint(f);
    return (u & 0x80000000u) ? ~u : (u | 0x80000000u);
}
__device__ __forceinline__ float finv(unsigned int u) {
    unsigned int b = (u & 0x80000000u) ? (u ^ 0x80000000u) : ~u;
    return __uint_as_float(b);
}

#define CSWAP(a, b) { if (k[b] > k[a]) { unsigned long long t = k[a]; k[a] = k[b]; k[b] = t; } }
#define SORT8_DESC() \
    CSWAP(0,1) CSWAP(2,3) CSWAP(4,5) CSWAP(6,7) \
    CSWAP(0,2) CSWAP(1,3) CSWAP(4,6) CSWAP(5,7) \
    CSWAP(1,2) CSWAP(5,6) CSWAP(0,4) CSWAP(3,7) \
    CSWAP(1,5) CSWAP(2,6) \
    CSWAP(1,4) CSWAP(3,6) \
    CSWAP(2,4) CSWAP(3,5) \
    CSWAP(3,4)

__device__ __forceinline__ void top32_of_256(
    const float* __restrict__ d, int lane, unsigned long long* __restrict__ sm,
    float& selv, int& seli)
{
    unsigned long long k[8];
#pragma unroll
    for (int r = 0; r < 8; r++) {
        int n = r * 32 + lane;
        k[r] = (((unsigned long long)fkey(d[n])) << 32) | (unsigned int)(~(unsigned int)n);
    }
    SORT8_DESC();
#pragma unroll
    for (int r = 0; r < 8; r++) sm[lane * 8 + r] = k[r];
    __syncwarp();

    int ptr = 0;
    float sv = 0.f; int si = 0;
    for (int i = 0; i < 32; i++) {
        unsigned long long h = (ptr < 8) ? sm[lane * 8 + ptr] : 0ULL;
        unsigned int hk = (unsigned int)(h >> 32);
        unsigned int vmax = __reduce_max_sync(0xFFFFFFFFu, hk);
        unsigned int n = ~(unsigned int)h;
        unsigned int aux = (hk == vmax) ? (256u - n) : 0u;       // min n among tied
        unsigned int amax = __reduce_max_sync(0xFFFFFFFFu, aux);
        unsigned int wn = 256u - amax;
        if (lane == (int)(wn & 31u)) ptr++;
        if (lane == i) { sv = finv(vmax); si = (int)wn; }
    }
    __syncwarp();
    selv = sv; seli = si;
}

// =================== fused top-k + softmax + gather: block = one token ===================
// Warps 0-3 extract p=0 per head, warps 4-7 extract p=1; warps 0-3 merge+softmax;
// then all 256 threads run the weighted gather (per-output chain r-ascending, bit-identical).
__global__ __launch_bounds__(256) void topk_gather_kernel(
    const float* __restrict__ dots, const float* __restrict__ values,
    float* __restrict__ out)
{
    const int token = blockIdx.x;
    const int wid = threadIdx.x >> 5;
    const int lane = threadIdx.x & 31;
    const int h = wid & 3;
    const bool isY = wid >= 4;

    __shared__ unsigned long long ssm[8][256];
    __shared__ float syv_s[4][32];
    __shared__ int   syi_s[4][32];
    __shared__ float sw[128];
    __shared__ int   si[128];

    const float* src = dots + (size_t)token * 2048 + h * 512 + (isY ? 256 : 0);

    float v; int idx;
    top32_of_256(src, lane, ssm[wid], v, idx);

    if (isY) { syv_s[h][lane] = v; syi_s[h][lane] = idx; }
    __syncthreads();

    if (!isY) {
        const float sxv = v;  const int sxi = idx;
        const float syv = syv_s[h][lane];
        const int   syi = syi_s[h][lane];

        int pj = 0;
        float fsv = 0.f; int fvidx = 0;
        for (int i = 0; i < 32; i++) {
            int srcl = (pj < 32) ? pj : 31;
            float sxp = __shfl_sync(0xFFFFFFFFu, sxv, srcl);
            float cand = __fadd_rn(sxp, syv);
            unsigned int ck = (pj < 32) ? fkey(cand) : 0u;
            unsigned int vmax = __reduce_max_sync(0xFFFFFFFFu, ck);
            unsigned int flat = (unsigned int)(pj * 32 + lane);
            unsigned int aux = (ck == vmax) ? (1024u - flat) : 0u;
            unsigned int amax = __reduce_max_sync(0xFFFFFFFFu, aux);
            unsigned int wf = 1024u - amax;
            int wi = (int)(wf >> 5), wj = (int)(wf & 31u);
            int ixv = __shfl_sync(0xFFFFFFFFu, sxi, wi);
            int iyv = __shfl_sync(0xFFFFFFFFu, syi, wj);
            if (lane == wj) pj++;
            if (lane == i) { fsv = finv(vmax); fvidx = ixv * 256 + iyv; }
        }

        const float mx = __shfl_sync(0xFFFFFFFFu, fsv, 0);
        const float e = expf(__fadd_rn(fsv, -mx));
        float ssum = e;
#pragma unroll
        for (int off = 16; off; off >>= 1) ssum += __shfl_xor_sync(0xFFFFFFFFu, ssum, off);
        const float w = __fdiv_rn(e, ssum);

        sw[h * 32 + lane] = w;
        si[h * 32 + lane] = fvidx;
    }
    __syncthreads();

    // ---- weighted gather: thread t owns output cols {2t, 2t+1}; r ascending ----
    const int t = threadIdx.x;
    float a0 = 0.f, a1 = 0.f;
#pragma unroll 8
    for (int r = 0; r < 128; r++) {
        const float2 vv = __ldg((const float2*)(values + (size_t)si[r] * 512) + t);
        const float wr = sw[r];
        a0 = fmaf(wr, vv.x, a0);
        a1 = fmaf(wr, vv.y, a1);
    }
    ((float2*)(out + (size_t)token * 512))[t] = make_float2(a0, a1);
}

// =================== launcher ===================
extern "C" void kernel_launch(void* const* d_in, const int* in_sizes, int n_in,
                              void* d_out, int out_size)
{
    const float* x      = (const float*)d_in[0];   // (2,2048,512)
    const float* wq     = (const float*)d_in[1];   // (1024,512)
    const float* ln_g   = (const float*)d_in[2];   // (128,)
    const float* ln_b   = (const float*)d_in[3];   // (128,)
    const float* keys   = (const float*)d_in[4];   // (4,256,2,128)
    const float* values = (const float*)d_in[5];   // (65536,512)
    float* out = (float*)d_out;

    float *qp, *dp;
    cudaGetSymbolAddress((void**)&qp, g_q);
    cudaGetSymbolAddress((void**)&dp, g_dots);

    // 1) q = x @ wq^T with fused LayerNorm epilogue
    gemm_asc_ln<<<dim3(DQ / QBN, TOK / QBM), 256>>>(x, DIMV, wq, DIMV, qp, DQ, DIMV, ln_g, ln_b);

    // 2) dots: all 8 (h,p) slices in one launch, 4 k-strided chains
    gemm_dots_s4<<<dim3(NKEY / BN, TOK / BM, 8), 256>>>(qp, keys, dp);

    // 3) fused top-k + softmax + weighted gather
    topk_gather_kernel<<<TOK, 256>>>(dp, values, out);
}

// round 15
// speedup vs baseline: 1.0891x; 1.0891x over previous
#include <cuda_runtime.h>
#include <cuda_bf16.h>
#include <math.h>

#define TOK   4096     // B*T
#define DIMV  512
#define DQ    1024
#define NKEY  256
#define DH    128
#define NHEAD 4

// ---------------- scratch (no allocations allowed) ----------------
__device__ float g_q[TOK * DQ];          // 16 MB
__device__ float g_dots[TOK * 2048];     // 32 MB  [token][h][p][n]
__device__ float g_w[TOK * 128];
__device__ int   g_vidx[TOK * 128];

// =================== q-proj GEMM: 128x128 tile, 8x8/thread, DOUBLE-BUFFERED smem ===================
// Per-output accumulation: k ascending, single fused-FMA chain (frozen numerics).
#define QBM 128
#define QBN 128
#define QBK 16

__global__ __launch_bounds__(256) void gemm_asc_128(
    const float* __restrict__ A, int lda,
    const float* __restrict__ B, int ldb,
    float* __restrict__ C, int ldc, int K)
{
    __shared__ float As[2][QBK][132];
    __shared__ float Bs[2][QBK][132];

    const int tid = threadIdx.x;
    const int tx = tid & 15;
    const int ty = tid >> 4;
    const int m0 = blockIdx.y * QBM;
    const int n0 = blockIdx.x * QBN;

    const int lrow = tid >> 1;
    const int lk   = (tid & 1) * 8;

    const float* Ab = A + (size_t)(m0 + lrow) * lda + lk;
    const float* Bb = B + (size_t)(n0 + lrow) * ldb + lk;

    float acc[8][8];
#pragma unroll
    for (int i = 0; i < 8; i++)
#pragma unroll
        for (int j = 0; j < 8; j++) acc[i][j] = 0.f;

    // preload tile 0 -> regs -> smem[0]
    float4 va0 = *(const float4*)(Ab);
    float4 va1 = *(const float4*)(Ab + 4);
    float4 vb0 = *(const float4*)(Bb);
    float4 vb1 = *(const float4*)(Bb + 4);
    As[0][lk + 0][lrow] = va0.x; As[0][lk + 1][lrow] = va0.y;
    As[0][lk + 2][lrow] = va0.z; As[0][lk + 3][lrow] = va0.w;
    As[0][lk + 4][lrow] = va1.x; As[0][lk + 5][lrow] = va1.y;
    As[0][lk + 6][lrow] = va1.z; As[0][lk + 7][lrow] = va1.w;
    Bs[0][lk + 0][lrow] = vb0.x; Bs[0][lk + 1][lrow] = vb0.y;
    Bs[0][lk + 2][lrow] = vb0.z; Bs[0][lk + 3][lrow] = vb0.w;
    Bs[0][lk + 4][lrow] = vb1.x; Bs[0][lk + 5][lrow] = vb1.y;
    Bs[0][lk + 6][lrow] = vb1.z; Bs[0][lk + 7][lrow] = vb1.w;
    __syncthreads();

    const int NT = K / QBK;
    for (int t = 0; t < NT; t++) {
        const int cur = t & 1;
        const int nxt = cur ^ 1;

        if (t + 1 < NT) {                 // global prefetch of tile t+1
            const int ko = (t + 1) * QBK;
            va0 = *(const float4*)(Ab + ko);
            va1 = *(const float4*)(Ab + ko + 4);
            vb0 = *(const float4*)(Bb + ko);
            vb1 = *(const float4*)(Bb + ko + 4);
        }

#pragma unroll
        for (int kk = 0; kk < QBK; kk++) {     // ascending k, fused chain (frozen)
            float a[8], b[8];
            *(float4*)(a)     = *(const float4*)(&As[cur][kk][ty * 8]);
            *(float4*)(a + 4) = *(const float4*)(&As[cur][kk][ty * 8 + 4]);
            *(float4*)(b)     = *(const float4*)(&Bs[cur][kk][tx * 8]);
            *(float4*)(b + 4) = *(const float4*)(&Bs[cur][kk][tx * 8 + 4]);
#pragma unroll
            for (int i = 0; i < 8; i++)
#pragma unroll
                for (int j = 0; j < 8; j++)
                    acc[i][j] = fmaf(a[i], b[j], acc[i][j]);
        }

        if (t + 1 < NT) {                 // stage tile t+1 into the other buffer
            As[nxt][lk + 0][lrow] = va0.x; As[nxt][lk + 1][lrow] = va0.y;
            As[nxt][lk + 2][lrow] = va0.z; As[nxt][lk + 3][lrow] = va0.w;
            As[nxt][lk + 4][lrow] = va1.x; As[nxt][lk + 5][lrow] = va1.y;
            As[nxt][lk + 6][lrow] = va1.z; As[nxt][lk + 7][lrow] = va1.w;
            Bs[nxt][lk + 0][lrow] = vb0.x; Bs[nxt][lk + 1][lrow] = vb0.y;
            Bs[nxt][lk + 2][lrow] = vb0.z; Bs[nxt][lk + 3][lrow] = vb0.w;
            Bs[nxt][lk + 4][lrow] = vb1.x; Bs[nxt][lk + 5][lrow] = vb1.y;
            Bs[nxt][lk + 6][lrow] = vb1.z; Bs[nxt][lk + 7][lrow] = vb1.w;
            __syncthreads();
        }
    }

#pragma unroll
    for (int i = 0; i < 8; i++) {
        float* Crow = C + (size_t)(m0 + ty * 8 + i) * ldc + n0 + tx * 8;
        *(float4*)(Crow)     = make_float4(acc[i][0], acc[i][1], acc[i][2], acc[i][3]);
        *(float4*)(Crow + 4) = make_float4(acc[i][4], acc[i][5], acc[i][6], acc[i][7]);
    }
}

// =================== dots GEMM: 4 k-strided fused chains, z-batched, reg-prefetched ===================
#define BM 64
#define BN 64
#define BK 16

__global__ __launch_bounds__(256) void gemm_dots_s4(
    const float* __restrict__ qbuf, const float* __restrict__ keys,
    float* __restrict__ dots)
{
    const int z = blockIdx.z;
    const int h = z >> 1, p = z & 1;
    const float* A = qbuf + (p * 4 + h) * 128;
    const float* B = keys + h * (NKEY * 2 * DH) + p * DH;
    float* C = dots + h * 512 + p * 256;
    const int lda = DQ, ldb = 2 * DH, ldc = 2048, K = DH;

    __shared__ float As[BK][BM];
    __shared__ float Bs[BK][BN];

    const int tid = threadIdx.x;
    const int tx = tid & 15;
    const int ty = tid >> 4;
    const int m0 = blockIdx.y * BM;
    const int n0 = blockIdx.x * BN;

    const int lrow = tid >> 2;
    const int lk   = (tid & 3) * 4;

    const float* Ab = A + (size_t)(m0 + lrow) * lda + lk;
    const float* Bb = B + (size_t)(n0 + lrow) * ldb + lk;

    float s[4][4][4];
#pragma unroll
    for (int i = 0; i < 4; i++)
#pragma unroll
        for (int j = 0; j < 4; j++)
#pragma unroll
            for (int c = 0; c < 4; c++) s[i][j][c] = 0.f;

    float4 va = *(const float4*)(Ab);
    float4 vb = *(const float4*)(Bb);

    for (int k0 = 0; k0 < K; k0 += BK) {
        As[lk + 0][lrow] = va.x; As[lk + 1][lrow] = va.y;
        As[lk + 2][lrow] = va.z; As[lk + 3][lrow] = va.w;
        Bs[lk + 0][lrow] = vb.x; Bs[lk + 1][lrow] = vb.y;
        Bs[lk + 2][lrow] = vb.z; Bs[lk + 3][lrow] = vb.w;
        __syncthreads();

        if (k0 + BK < K) {
            va = *(const float4*)(Ab + k0 + BK);
            vb = *(const float4*)(Bb + k0 + BK);
        }

#pragma unroll
        for (int kk = 0; kk < BK; kk++) {
            const int ch = kk & 3;
            float a[4], b[4];
#pragma unroll
            for (int i = 0; i < 4; i++) a[i] = As[kk][ty * 4 + i];
#pragma unroll
            for (int j = 0; j < 4; j++) b[j] = Bs[kk][tx * 4 + j];
#pragma unroll
            for (int i = 0; i < 4; i++)
#pragma unroll
                for (int j = 0; j < 4; j++)
                    s[i][j][ch] = fmaf(a[i], b[j], s[i][j][ch]);
        }
        __syncthreads();
    }

#pragma unroll
    for (int i = 0; i < 4; i++) {
        float* Crow = C + (size_t)(m0 + ty * 4 + i) * ldc + n0 + tx * 4;
#pragma unroll
        for (int j = 0; j < 4; j++) {
            float p01 = __fadd_rn(s[i][j][0], s[i][j][1]);
            float p23 = __fadd_rn(s[i][j][2], s[i][j][3]);
            Crow[j] = __fadd_rn(p01, p23);
        }
    }
}

// =================== LayerNorm: sequential fp32, non-fused (proven neutral) ===================
#define LN_ROWS 64

__global__ __launch_bounds__(LN_ROWS) void ln_kernel(
    float* __restrict__ q, const float* __restrict__ g, const float* __restrict__ b)
{
    __shared__ float sm[LN_ROWS * 129];
    __shared__ float sg[128], sb[128];
    const int t = threadIdx.x;
    const size_t base = (size_t)blockIdx.x * LN_ROWS * 128;

    for (int i = t; i < LN_ROWS * 128; i += LN_ROWS) {
        int r = i >> 7, c = i & 127;
        sm[r * 129 + c] = q[base + i];
    }
    for (int i = t; i < 128; i += LN_ROWS) { sg[i] = g[i]; sb[i] = b[i]; }
    __syncthreads();

    float* row = sm + t * 129;
    float s = 0.f;
#pragma unroll 8
    for (int i = 0; i < 128; i++) s = __fadd_rn(s, row[i]);
    const float mu = __fdiv_rn(s, 128.0f);

    float ss = 0.f;
#pragma unroll 8
    for (int i = 0; i < 128; i++) {
        float d = __fadd_rn(row[i], -mu);
        ss = __fadd_rn(ss, __fmul_rn(d, d));
    }
    const float var = __fdiv_rn(ss, 128.0f);
    const float r = __fdiv_rn(1.0f, sqrtf(__fadd_rn(var, 1e-5f)));

#pragma unroll 8
    for (int i = 0; i < 128; i++) {
        float d = __fadd_rn(row[i], -mu);
        row[i] = __fadd_rn(__fmul_rn(__fmul_rn(d, r), sg[i]), sb[i]);
    }
    __syncthreads();

    for (int i = t; i < LN_ROWS * 128; i += LN_ROWS) {
        int r2 = i >> 7, c = i & 127;
        q[base + i] = sm[r2 * 129 + c];
    }
}

// =================== top-k machinery (R11 two-REDUX version — known good) ===================
__device__ __forceinline__ unsigned int fkey(float f) {
    unsigned int u = __float_as_uint(f);
    return (u & 0x80000000u) ? ~u : (u | 0x80000000u);
}
__device__ __forceinline__ float finv(unsigned int u) {
    unsigned int b = (u & 0x80000000u) ? (u ^ 0x80000000u) : ~u;
    return __uint_as_float(b);
}

#define CSWAP(a, b) { if (k[b] > k[a]) { unsigned long long t = k[a]; k[a] = k[b]; k[b] = t; } }
#define SORT8_DESC() \
    CSWAP(0,1) CSWAP(2,3) CSWAP(4,5) CSWAP(6,7) \
    CSWAP(0,2) CSWAP(1,3) CSWAP(4,6) CSWAP(5,7) \
    CSWAP(1,2) CSWAP(5,6) CSWAP(0,4) CSWAP(3,7) \
    CSWAP(1,5) CSWAP(2,6) \
    CSWAP(1,4) CSWAP(3,6) \
    CSWAP(2,4) CSWAP(3,5) \
    CSWAP(3,4)

__device__ __forceinline__ void top32_of_256(
    const float* __restrict__ d, int lane, unsigned long long* __restrict__ sm,
    float& selv, int& seli)
{
    unsigned long long k[8];
#pragma unroll
    for (int r = 0; r < 8; r++) {
        int n = r * 32 + lane;
        k[r] = (((unsigned long long)fkey(d[n])) << 32) | (unsigned int)(~(unsigned int)n);
    }
    SORT8_DESC();
#pragma unroll
    for (int r = 0; r < 8; r++) sm[lane * 8 + r] = k[r];
    __syncwarp();

    int ptr = 0;
    float sv = 0.f; int si = 0;
    for (int i = 0; i < 32; i++) {
        unsigned long long h = (ptr < 8) ? sm[lane * 8 + ptr] : 0ULL;
        unsigned int hk = (unsigned int)(h >> 32);
        unsigned int vmax = __reduce_max_sync(0xFFFFFFFFu, hk);
        unsigned int n = ~(unsigned int)h;
        unsigned int aux = (hk == vmax) ? (256u - n) : 0u;
        unsigned int amax = __reduce_max_sync(0xFFFFFFFFu, aux);
        unsigned int wn = 256u - amax;
        if (lane == (int)(wn & 31u)) ptr++;
        if (lane == i) { sv = finv(vmax); si = (int)wn; }
    }
    __syncwarp();
    selv = sv; seli = si;
}

// block = one token, 8 warps: warps 0-3 extract p=0, warps 4-7 extract p=1, warps 0-3 merge.
__global__ __launch_bounds__(256) void topk_kernel(
    const float* __restrict__ dots, float* __restrict__ wout, int* __restrict__ vout)
{
    const int token = blockIdx.x;
    const int wid = threadIdx.x >> 5;
    const int lane = threadIdx.x & 31;
    const int h = wid & 3;
    const bool isY = wid >= 4;

    __shared__ unsigned long long ssm[8][256];
    __shared__ float syv_s[4][32];
    __shared__ int   syi_s[4][32];

    const float* src = dots + (size_t)token * 2048 + h * 512 + (isY ? 256 : 0);

    float v; int idx;
    top32_of_256(src, lane, ssm[wid], v, idx);

    if (isY) { syv_s[h][lane] = v; syi_s[h][lane] = idx; }
    __syncthreads();

    if (!isY) {
        const float sxv = v;  const int sxi = idx;
        const float syv = syv_s[h][lane];
        const int   syi = syi_s[h][lane];

        int pj = 0;
        float fsv = 0.f; int fvidx = 0;
        for (int i = 0; i < 32; i++) {
            int srcl = (pj < 32) ? pj : 31;
            float sxp = __shfl_sync(0xFFFFFFFFu, sxv, srcl);
            float cand = __fadd_rn(sxp, syv);
            unsigned int ck = (pj < 32) ? fkey(cand) : 0u;
            unsigned int vmax = __reduce_max_sync(0xFFFFFFFFu, ck);
            unsigned int flat = (unsigned int)(pj * 32 + lane);
            unsigned int aux = (ck == vmax) ? (1024u - flat) : 0u;
            unsigned int amax = __reduce_max_sync(0xFFFFFFFFu, aux);
            unsigned int wf = 1024u - amax;
            int wi = (int)(wf >> 5), wj = (int)(wf & 31u);
            int ixv = __shfl_sync(0xFFFFFFFFu, sxi, wi);
            int iyv = __shfl_sync(0xFFFFFFFFu, syi, wj);
            if (lane == wj) pj++;
            if (lane == i) { fsv = finv(vmax); fvidx = ixv * 256 + iyv; }
        }

        const float mx = __shfl_sync(0xFFFFFFFFu, fsv, 0);
        const float e = expf(__fadd_rn(fsv, -mx));
        float ssum = e;
#pragma unroll
        for (int off = 16; off; off >>= 1) ssum += __shfl_xor_sync(0xFFFFFFFFu, ssum, off);
        const float w = __fdiv_rn(e, ssum);

        const int base = (token * 4 + h) * 32 + lane;
        wout[base] = w;
        vout[base] = fvidx;
    }
}

// =================== weighted gather: ascending fused chain ===================
__global__ __launch_bounds__(128) void gather_kernel(
    const float* __restrict__ values, const float* __restrict__ w,
    const int* __restrict__ vidx, float* __restrict__ out)
{
    const int token = blockIdx.x;
    const int t = threadIdx.x;
    __shared__ float sw[128];
    __shared__ int   si[128];
    sw[t] = w[(size_t)token * 128 + t];
    si[t] = vidx[(size_t)token * 128 + t];
    __syncthreads();

    float4 acc = make_float4(0.f, 0.f, 0.f, 0.f);
#pragma unroll 8
    for (int r = 0; r < 128; r++) {
        const float4* row = (const float4*)(values + (size_t)si[r] * 512);
        float4 v = __ldg(&row[t]);
        float wr = sw[r];
        acc.x = fmaf(wr, v.x, acc.x); acc.y = fmaf(wr, v.y, acc.y);
        acc.z = fmaf(wr, v.z, acc.z); acc.w = fmaf(wr, v.w, acc.w);
    }
    ((float4*)(out + (size_t)token * 512))[t] = acc;
}

// =================== launcher ===================
extern "C" void kernel_launch(void* const* d_in, const int* in_sizes, int n_in,
                              void* d_out, int out_size)
{
    const float* x      = (const float*)d_in[0];   // (2,2048,512)
    const float* wq     = (const float*)d_in[1];   // (1024,512)
    const float* ln_g   = (const float*)d_in[2];   // (128,)
    const float* ln_b   = (const float*)d_in[3];   // (128,)
    const float* keys   = (const float*)d_in[4];   // (4,256,2,128)
    const float* values = (const float*)d_in[5];   // (65536,512)
    float* out = (float*)d_out;

    float *qp, *dp, *wp; int* ip;
    cudaGetSymbolAddress((void**)&qp, g_q);
    cudaGetSymbolAddress((void**)&dp, g_dots);
    cudaGetSymbolAddress((void**)&wp, g_w);
    cudaGetSymbolAddress((void**)&ip, g_vidx);

    // 1) q = x @ wq^T : ascending fused chain, double-buffered 128x128 tiles
    gemm_asc_128<<<dim3(DQ / QBN, TOK / QBM), 256>>>(x, DIMV, wq, DIMV, qp, DQ, DIMV);

    // 2) layernorm per 128-vector (in place)
    ln_kernel<<<(TOK * 8) / LN_ROWS, LN_ROWS>>>(qp, ln_g, ln_b);

    // 3) dots: all 8 (h,p) slices in one launch, 4 k-strided chains
    gemm_dots_s4<<<dim3(NKEY / BN, TOK / BM, 8), 256>>>(qp, keys, dp);

    // 4) top-k + combine + softmax (R11 structure)
    topk_kernel<<<TOK, 256>>>(dp, wp, ip);

    // 5) weighted value gather
    gather_kernel<<<TOK, 128>>>(values, wp, ip, out);
}